// round 17
// baseline (speedup 1.0000x reference)
#include <cuda_runtime.h>
#include <cuda_fp16.h>
#include <cstdint>

// GraphAttentionLayer — all-tensor-core pipeline.
//   conv:  g_hh = fp16(h), g_W16 = fp16(W)
//   gemm:  g_Whh = fp16(g_hh @ g_W16)   (mma.sync fp16, cp.async-pipelined A)
//   attn:  flash attention, DELAYED-PV pipeline: at iter t the warp issues
//          S(t) and PV(t-1) mma interleaved (one long independent burst),
//          then computes ph(t). 4 smem buffers. Row-sums via ones-MMA.
//          Folded leaky+exp in log2 domain; exp(y-8) shift softmax.

#define T_LEN   2048
#define B_SZ    8
#define H_CNT   4
#define D_DIM   64
#define IN_DIM  256
#define M_TOT   (B_SZ * T_LEN)

#define ONES2 0x3C003C00u   // fp16x2 {1.0, 1.0}

__device__ __half g_hh [(size_t)M_TOT * IN_DIM];   // 8 MB   fp16 h
__device__ __half g_W16[(size_t)IN_DIM * IN_DIM];  // 128 KB fp16 W
__device__ __half g_Whh[(size_t)M_TOT * IN_DIM];   // 8 MB   fp16 Wh

// ---------------------------------------------------------------------------
__device__ __forceinline__ uint32_t packh2(float lo, float hi) {
    uint32_t d;
    asm("cvt.rn.f16x2.f32 %0, %1, %2;" : "=r"(d) : "f"(hi), "f"(lo));
    return d;
}
__device__ __forceinline__ void mma16(float* c, const uint32_t* a,
                                      uint32_t b0, uint32_t b1) {
    asm volatile(
        "mma.sync.aligned.m16n8k16.row.col.f32.f16.f16.f32 "
        "{%0,%1,%2,%3}, {%4,%5,%6,%7}, {%8,%9}, {%0,%1,%2,%3};"
        : "+f"(c[0]), "+f"(c[1]), "+f"(c[2]), "+f"(c[3])
        : "r"(a[0]), "r"(a[1]), "r"(a[2]), "r"(a[3]), "r"(b0), "r"(b1));
}
// exp(leaky(s/8) - 8) = 2^( max(s, 0.2s)*log2e/8 - 8*log2e )
__device__ __forceinline__ float lexp(float s) {
    float m = fmaxf(s, 0.2f * s);
    float t = fmaf(m, 0.18033688011112043f, -11.541560327111708f);
    float r;
    asm("ex2.approx.ftz.f32 %0, %1;" : "=f"(r) : "f"(t));
    return r;
}
__device__ __forceinline__ uint32_t smem_addr(const void* p) {
    uint32_t a;
    asm("{ .reg .u64 t; cvta.to.shared.u64 t, %1; cvt.u32.u64 %0, t; }" : "=r"(a) : "l"(p));
    return a;
}
__device__ __forceinline__ void ldsm4(uint32_t& r0, uint32_t& r1, uint32_t& r2,
                                      uint32_t& r3, uint32_t addr) {
    asm volatile("ldmatrix.sync.aligned.m8n8.x4.shared.b16 {%0,%1,%2,%3}, [%4];"
                 : "=r"(r0), "=r"(r1), "=r"(r2), "=r"(r3) : "r"(addr));
}
__device__ __forceinline__ void ldsm4t(uint32_t& r0, uint32_t& r1, uint32_t& r2,
                                       uint32_t& r3, uint32_t addr) {
    asm volatile("ldmatrix.sync.aligned.m8n8.x4.trans.shared.b16 {%0,%1,%2,%3}, [%4];"
                 : "=r"(r0), "=r"(r1), "=r"(r2), "=r"(r3) : "r"(addr));
}
#define CP_ASYNC16(dst, src) \
    asm volatile("cp.async.cg.shared.global [%0], [%1], 16;" :: "r"(dst), "l"(src) : "memory")
#define CP_COMMIT() asm volatile("cp.async.commit_group;" ::: "memory")
#define CP_WAIT1()  asm volatile("cp.async.wait_group 1;" ::: "memory")
#define CP_WAIT0()  asm volatile("cp.async.wait_group 0;" ::: "memory")

// ---------------------------------------------------------------------------
// conv: fp32 -> fp16 for h and W
// ---------------------------------------------------------------------------
#define H4  ((M_TOT * IN_DIM) / 4)
#define W4  ((IN_DIM * IN_DIM) / 4)

__global__ void __launch_bounds__(256) gat_conv_kernel(
    const float4* __restrict__ h4, const float4* __restrict__ w4)
{
    const int i = blockIdx.x * 256 + threadIdx.x;
    if (i < H4) {
        float4 v = h4[i];
        ((uint2*)g_hh)[i] = make_uint2(packh2(v.x, v.y), packh2(v.z, v.w));
    } else if (i < H4 + W4) {
        const int j = i - H4;
        float4 v = w4[j];
        ((uint2*)g_W16)[j] = make_uint2(packh2(v.x, v.y), packh2(v.z, v.w));
    }
}

// ---------------------------------------------------------------------------
// Tensor GEMM: g_Whh[16384,256] = g_hh @ g_W16.  Grid (128, 4), 128 thr.
// W col-tile resident (32 KB, chunk c of row r at c^(r&7)); A streamed via
// triple-buffered cp.async 4 KB chunks (unit u = khalf*128 + row).
// ---------------------------------------------------------------------------
#define GW_WORDS 8192
#define GA_WORDS 1024
#define GA_BYTES 4096

__global__ void __launch_bounds__(128) gat_gemm_tc()
{
    __shared__ uint32_t smw[GW_WORDS + 3 * GA_WORDS];   // 44 KB
    const int tid = threadIdx.x;
    const int w   = tid >> 5;
    const int l   = tid & 31;
    const int g   = l >> 2;
    const int tig = l & 3;
    const int m0  = blockIdx.x * 128;
    const int n0  = blockIdx.y * 64;

    const uint32_t smbase = smem_addr(smw);
    const uint32_t abase  = smbase + GW_WORDS * 4;

#pragma unroll
    for (int rr = 0; rr < 2; rr++) {
        const int r = tid + 128 * rr;
        const char* src = (const char*)(g_W16 + (size_t)r * IN_DIM + n0);
#pragma unroll
        for (int c = 0; c < 8; c++)
            CP_ASYNC16(smbase + (uint32_t)(r * 128 + (((uint32_t)c ^ (r & 7)) << 4)),
                       src + 16 * c);
    }
    CP_COMMIT();

    const int au0 = tid, au1 = tid + 128;
    const int ac0 = au0 >> 7, ar0 = au0 & 127;
    const int ac1 = au1 >> 7, ar1 = au1 & 127;
    const char* asrc0 = (const char*)(g_hh + (size_t)(m0 + ar0) * IN_DIM + ac0 * 8);
    const char* asrc1 = (const char*)(g_hh + (size_t)(m0 + ar1) * IN_DIM + ac1 * 8);

#pragma unroll
    for (int k = 0; k < 2; k++) {
        const uint32_t bofs = (uint32_t)(k * GA_BYTES);
        CP_ASYNC16(abase + bofs + au0 * 16, asrc0 + (size_t)k * 32);
        CP_ASYNC16(abase + bofs + au1 * 16, asrc1 + (size_t)k * 32);
        CP_COMMIT();
    }

    float o[2][8][4];
#pragma unroll
    for (int hh = 0; hh < 2; hh++)
#pragma unroll
        for (int i = 0; i < 8; i++)
#pragma unroll
            for (int j = 0; j < 4; j++) o[hh][i][j] = 0.f;

    const uint32_t lk7  = (uint32_t)(l & 7);
    const int vKey = (((l >> 3) & 1) << 3) + (l & 7);
    const uint32_t vJ = (uint32_t)(l >> 4);
    const int aRow = w * 32 + (l & 15);
    const int aCol = l >> 4;

#pragma unroll
    for (int ks = 0; ks < 16; ks++) {
        if (ks < 15) CP_WAIT1(); else CP_WAIT0();
        __syncthreads();
        if (ks <= 13) {
            const uint32_t bofs = (uint32_t)(((ks + 2) % 3) * GA_BYTES);
            CP_ASYNC16(abase + bofs + au0 * 16, asrc0 + (size_t)(ks + 2) * 32);
            CP_ASYNC16(abase + bofs + au1 * 16, asrc1 + (size_t)(ks + 2) * 32);
            CP_COMMIT();
        }

        const uint32_t ab = abase + (uint32_t)((ks % 3) * GA_BYTES);
        uint32_t aa[2][4];
#pragma unroll
        for (int hh = 0; hh < 2; hh++)
            ldsm4(aa[hh][0], aa[hh][1], aa[hh][2], aa[hh][3],
                  ab + (uint32_t)(((aCol << 7) + aRow + hh * 16) << 4));

#pragma unroll
        for (int i = 0; i < 4; i++) {
            uint32_t r0, r1, r2, r3;
            const uint32_t addr = smbase + (uint32_t)((16 * ks + vKey) * 128
                                   + ((((uint32_t)(2 * i) + vJ) ^ lk7) << 4));
            ldsm4t(r0, r1, r2, r3, addr);
#pragma unroll
            for (int hh = 0; hh < 2; hh++) {
                mma16(o[hh][2 * i],     aa[hh], r0, r1);
                mma16(o[hh][2 * i + 1], aa[hh], r2, r3);
            }
        }
        __syncthreads();
    }

#pragma unroll
    for (int hh = 0; hh < 2; hh++) {
        const int row0 = m0 + w * 32 + hh * 16 + g;
        __half* p0 = g_Whh + (size_t)row0 * IN_DIM + n0;
        __half* p1 = p0 + 8 * IN_DIM;
#pragma unroll
        for (int j = 0; j < 8; j++) {
            const int col = 8 * j + 2 * tig;
            *(uint32_t*)(p0 + col) = packh2(o[hh][j][0], o[hh][j][1]);
            *(uint32_t*)(p1 + col) = packh2(o[hh][j][2], o[hh][j][3]);
        }
    }
}

// ---------------------------------------------------------------------------
// Flash attention, delayed-PV pipeline. CTA = 128 thr (4 warps), warp = m16.
// CTA = 64 queries. Grid (32, 32). Key-tile 64, 32 tiles, 4 smem buffers.
// Iter t: wait(tile t) -> barrier -> prefetch(t+2) -> [S(t) ⋈ PV(t-1) mma
// burst] -> epilogue ph(t). Tail PV(31) after the loop.
// Tile: row = key (64 x 128B), chunk c of row r at (c ^ (r & 7)).
// ---------------------------------------------------------------------------
#define BUF_BYTES 8192

__global__ void __launch_bounds__(128, 3) gat_attn_mma(float* __restrict__ out)
{
    __shared__ uint32_t smu[4 * BUF_BYTES / 4];   // 32 KB

    const int tid = threadIdx.x;
    const int w   = tid >> 5;
    const int l   = tid & 31;
    const int g   = l >> 2;
    const int tig = l & 3;

    const int bh = blockIdx.y, b = bh >> 2, head = bh & 3;
    const int qbase = blockIdx.x * 64;
    const __half* whh = g_Whh + (size_t)b * T_LEN * IN_DIM + head * D_DIM;

    const uint32_t smbase = smem_addr(smu);

    // fill setup (thread = half-row): 4 x cp.async 16B per tile
    const int frow = tid >> 1, fhf = tid & 1;
    const char* fsrc0 = (const char*)(whh + (size_t)frow * IN_DIM + fhf * 32);
    uint32_t fdst[4];
#pragma unroll
    for (int j = 0; j < 4; j++) {
        const int c = fhf * 4 + j;
        fdst[j] = smbase + (uint32_t)(frow * 128 + ((c ^ (frow & 7)) << 4));
    }

    // prologue: prefetch tiles 0 and 1
#pragma unroll
    for (int k = 0; k < 2; k++) {
        const char* s = fsrc0 + (size_t)k * 64 * IN_DIM * sizeof(__half);
        const uint32_t bofs = (uint32_t)(k * BUF_BYTES);
#pragma unroll
        for (int j = 0; j < 4; j++) CP_ASYNC16(fdst[j] + bofs, s + 16 * j);
        CP_COMMIT();
    }

    // Q fragments (warp = rows qbase + w*16 + g, +8)
    uint32_t qa[4][4];
    {
        const uint32_t* q0 = (const uint32_t*)(whh + (size_t)(qbase + w * 16 + g) * IN_DIM);
        const uint32_t* q1 = q0 + 8 * (IN_DIM / 2);
#pragma unroll
        for (int ks = 0; ks < 4; ks++) {
            qa[ks][0] = q0[8 * ks + tig];
            qa[ks][1] = q1[8 * ks + tig];
            qa[ks][2] = q0[8 * ks + 4 + tig];
            qa[ks][3] = q1[8 * ks + 4 + tig];
        }
    }

    float o[8][4];
#pragma unroll
    for (int i = 0; i < 8; i++)
#pragma unroll
        for (int j = 0; j < 4; j++) o[i][j] = 0.f;
    float lsacc[4] = {0.f, 0.f, 0.f, 0.f};
    uint32_t ph[8][2];   // P of the PREVIOUS tile (valid for t >= 1)

    const uint32_t lk7  = (uint32_t)(l & 7);
    const int sKey = ((l >> 4) << 3) + (l & 7);
    const uint32_t sSeg = (uint32_t)((l >> 3) & 1);
    const int vKey = (((l >> 3) & 1) << 3) + (l & 7);
    const uint32_t vJ  = (uint32_t)(l >> 4);

    for (int t = 0; t < 32; t++) {
        if (t < 31) CP_WAIT1(); else CP_WAIT0();
        __syncthreads();
        // prefetch t+2 into (t+2)%4 (== (t-2)%4, last read by S(t-2)/PV(t-1),
        // both complete before the barrier above).
        if (t <= 29) {
            const uint32_t bofs = (uint32_t)(((t + 2) & 3) * BUF_BYTES);
            const char* s = fsrc0 + (size_t)(t + 2) * 64 * IN_DIM * sizeof(__half);
#pragma unroll
            for (int j = 0; j < 4; j++) CP_ASYNC16(fdst[j] + bofs, s + 16 * j);
            CP_COMMIT();
        }

        const uint32_t bbS = smbase + (uint32_t)((t & 3) * BUF_BYTES);
        const uint32_t bbV = smbase + (uint32_t)(((t + 3) & 3) * BUF_BYTES);

        // ---- merged burst: S(t) and PV(t-1), interleaved per ks
        float s2[8][4];
#pragma unroll
        for (int i = 0; i < 8; i++)
#pragma unroll
            for (int j = 0; j < 4; j++) s2[i][j] = 0.f;

#pragma unroll
        for (int ks = 0; ks < 4; ks++) {
            // S(t), k-step ks: 4 ldsm + 8 mma
#pragma unroll
            for (int i = 0; i < 4; i++) {
                uint32_t r0, r1, r2, r3;
                const uint32_t addr = bbS + (uint32_t)((16 * i + sKey) * 128
                                       + ((((uint32_t)(2 * ks) + sSeg) ^ lk7) << 4));
                ldsm4(r0, r1, r2, r3, addr);
                mma16(s2[2 * i],     qa[ks], r0, r1);
                mma16(s2[2 * i + 1], qa[ks], r2, r3);
            }
            // PV(t-1), k-step ks: 4 ldsmt + 9 mma
            if (t) {
                uint32_t pa[4] = { ph[2 * ks][0], ph[2 * ks][1],
                                   ph[2 * ks + 1][0], ph[2 * ks + 1][1] };
#pragma unroll
                for (int i = 0; i < 4; i++) {
                    uint32_t r0, r1, r2, r3;
                    const uint32_t addr = bbV + (uint32_t)((16 * ks + vKey) * 128
                                           + ((((uint32_t)(2 * i) + vJ) ^ lk7) << 4));
                    ldsm4t(r0, r1, r2, r3, addr);
                    mma16(o[2 * i],     pa, r0, r1);
                    mma16(o[2 * i + 1], pa, r2, r3);
                }
                mma16(lsacc, pa, ONES2, ONES2);
            }
        }

        // ---- epilogue: ph(t) from s2
#pragma unroll
        for (int j = 0; j < 8; j++) {
            float p0 = lexp(s2[j][0]);
            float p1 = lexp(s2[j][1]);
            float p2 = lexp(s2[j][2]);
            float p3 = lexp(s2[j][3]);
            ph[j][0] = packh2(p0, p1);
            ph[j][1] = packh2(p2, p3);
        }
    }

    // ---- tail: PV(31) from buffer 31%4 = 3 (not overwritten; no barrier needed)
    {
        const uint32_t bbV = smbase + (uint32_t)(3 * BUF_BYTES);
#pragma unroll
        for (int ks = 0; ks < 4; ks++) {
            uint32_t pa[4] = { ph[2 * ks][0], ph[2 * ks][1],
                               ph[2 * ks + 1][0], ph[2 * ks + 1][1] };
#pragma unroll
            for (int i = 0; i < 4; i++) {
                uint32_t r0, r1, r2, r3;
                const uint32_t addr = bbV + (uint32_t)((16 * ks + vKey) * 128
                                       + ((((uint32_t)(2 * i) + vJ) ^ lk7) << 4));
                ldsm4t(r0, r1, r2, r3, addr);
                mma16(o[2 * i],     pa, r0, r1);
                mma16(o[2 * i + 1], pa, r2, r3);
            }
            mma16(lsacc, pa, ONES2, ONES2);
        }
    }

    // ---- normalize + write (lsacc c0 = row g, c2 = row g+8)
    {
        const float inv0 = 1.0f / lsacc[0];
        const float inv1 = 1.0f / lsacc[2];
        const int row0 = qbase + w * 16 + g;
        float* p0 = out + (size_t)(b * T_LEN + row0) * IN_DIM + head * D_DIM;
        float* p1 = p0 + 8 * IN_DIM;
#pragma unroll
        for (int i = 0; i < 8; i++) {
            const int col = i * 8 + 2 * tig;
            *(float2*)(p0 + col) = make_float2(o[i][0] * inv0, o[i][1] * inv0);
            *(float2*)(p1 + col) = make_float2(o[i][2] * inv1, o[i][3] * inv1);
        }
    }
}

// ---------------------------------------------------------------------------

extern "C" void kernel_launch(void* const* d_in, const int* in_sizes, int n_in,
                              void* d_out, int out_size)
{
    const float* h = (const float*)d_in[0];
    const float* W = (const float*)d_in[1];
    float* out = (float*)d_out;

    gat_conv_kernel<<<(H4 + W4 + 255) / 256, 256>>>((const float4*)h, (const float4*)W);

    dim3 gg(M_TOT / 128, IN_DIM / 64);          // (128, 4)
    gat_gemm_tc<<<gg, 128>>>();

    dim3 g2(T_LEN / 64, B_SZ * H_CNT);          // (32, 32)
    gat_attn_mma<<<g2, 128>>>(out);
}